// round 7
// baseline (speedup 1.0000x reference)
#include <cuda_runtime.h>

// ConvDecoder: 2-layer ConvLSTM decoder.
// fp32 conv, FFMA2 (fma.rn.f32x2), 64x32 tile, 8 oc/block, 8 px/thread,
// double-buffered halo. B=8, T=10, C=64, CH=128, H=W=64, 3x3 SAME.

#define BB 8
#define TT 10
#define CX 64
#define CH 128
#define WW 64
#define HW 4096
#define GG (4*CH)   // 512 gate channels

// ---- persistent scratch (device globals; no allocation allowed) ----
__device__ float g_h0[BB*CH*HW];
__device__ float g_c0[BB*CH*HW];
__device__ float g_h1[BB*CH*HW];
__device__ float g_c1[BB*CH*HW];
__device__ float g_gates[BB*GG*HW];

// ---- packed f32x2 helpers ----
static __device__ __forceinline__ unsigned long long pack2(float lo, float hi) {
    unsigned long long r;
    asm("mov.b64 %0, {%1, %2};" : "=l"(r) : "f"(lo), "f"(hi));
    return r;
}
static __device__ __forceinline__ void fma2(unsigned long long& d,
                                            unsigned long long a,
                                            unsigned long long b) {
    asm("fma.rn.f32x2 %0, %1, %2, %0;" : "+l"(d) : "l"(a), "l"(b));
}
static __device__ __forceinline__ float2 unpack2(unsigned long long v) {
    float2 r;
    asm("mov.b64 {%0, %1}, %2;" : "=f"(r.x), "=f"(r.y) : "l"(v));
    return r;
}

__global__ void init_states(const float* __restrict__ h0, const float* __restrict__ c0,
                            const float* __restrict__ h1, const float* __restrict__ c1) {
    int n = BB*CH*HW;
    for (int i = blockIdx.x*blockDim.x + threadIdx.x; i < n; i += gridDim.x*blockDim.x) {
        g_h0[i] = h0[i];
        g_c0[i] = c0[i];
        g_h1[i] = h1[i];
        g_c1[i] = c1[i];
    }
}

// ---- fused 3x3 conv: out = conv(in1,w1)+b1 [+ conv(in2,w2)+b2] ----
// Tile: 64 wide (full row) x 32 tall, 8 output channels/block, 256 threads.
// Thread (x = tid&63, ty = tid>>6) computes rows ty*8..ty*8+7 at col x,
// packed as 4 vertical f32x2 pairs, for all 8 output channels.
#define SROW 72           // smem floats per row (data cols at 3..68 = gx -1..64)
#define SROWS 34
#define SBUF (SROWS*SROW) // 2448 floats

__global__ __launch_bounds__(256, 1)
void conv3x3_kernel(const float* __restrict__ in1, int cin1, long in1_bstride,
                    const float* __restrict__ w1, const float* __restrict__ b1,
                    const float* __restrict__ in2, int cin2,
                    const float* __restrict__ w2, const float* __restrict__ b2,
                    float* __restrict__ out, long out_bstride)
{
    __shared__ float  s_in[2][SBUF];
    __shared__ float2 s_w[2][72];

    const int tid   = threadIdx.x;
    const int ytile = blockIdx.x;          // 0..1
    const int oBase = blockIdx.y * 8;
    const int b     = blockIdx.z;
    const int x     = tid & 63;
    const int ty    = tid >> 6;            // 0..3
    const int y0    = ytile * 32;
    const int r0    = ty * 8;              // local output row base

    // zero both input buffers once (constant halo zeros stay valid)
    for (int i = tid; i < 2*SBUF; i += 256) ((float*)s_in)[i] = 0.f;

    // halo descriptors: 33 valid gmem rows x 16 float4 each = 528 loads
    const int sbase = (ytile == 0) ? 1 : 0;   // smem row of first valid gy
    const int gy0   = (ytile == 0) ? 0 : 31;  // first valid gy
    int henc[3];
#pragma unroll
    for (int j2 = 0; j2 < 3; ++j2) {
        int i  = tid + j2*256;
        int rr = i >> 4, q = i & 15;
        bool ok = (rr < 33);
        int soff = (sbase + rr)*SROW + 4 + q*4;   // <= 2440, 12 bits
        int goff = (gy0 + rr)*WW + q*4;           // <= 4092, 12 bits
        henc[j2] = ok ? (soff | (goff << 12) | (1 << 25)) : 0;
    }

    const int  oo_w   = tid / 9;
    const int  k_w    = tid - oo_w*9;
    const bool w_role = tid < 72;

    const float* in1b = in1 + (long)b * in1_bstride;
    const float* in2b = in2 ? (in2 + (long)b * ((long)CH*HW)) : nullptr;
    const int totalCin = cin1 + cin2;

    unsigned long long acc[32];
    const unsigned long long z = pack2(0.f, 0.f);
#pragma unroll
    for (int i = 0; i < 32; ++i) acc[i] = z;

    float4 pre0, pre1, pre2;
    float  wpre = 0.f;

    auto fetch = [&](int j) {
        const float* ic = (j < cin1) ? (in1b + (long)j*HW)
                                     : (in2b + (long)(j - cin1)*HW);
        if (henc[0] >> 25) pre0 = *(const float4*)(ic + ((henc[0] >> 12) & 0xFFF));
        if (henc[1] >> 25) pre1 = *(const float4*)(ic + ((henc[1] >> 12) & 0xFFF));
        if (henc[2] >> 25) pre2 = *(const float4*)(ic + ((henc[2] >> 12) & 0xFFF));
        if (w_role) {
            if (j < cin1) wpre = w1[((oBase + oo_w)*cin1 + j)*9 + k_w];
            else          wpre = w2[((oBase + oo_w)*cin2 + (j - cin1))*9 + k_w];
        }
    };
    auto store = [&](int buf) {
        if (henc[0] >> 25) *(float4*)&s_in[buf][henc[0] & 0xFFF] = pre0;
        if (henc[1] >> 25) *(float4*)&s_in[buf][henc[1] & 0xFFF] = pre1;
        if (henc[2] >> 25) *(float4*)&s_in[buf][henc[2] & 0xFFF] = pre2;
        if (w_role) s_w[buf][tid] = make_float2(wpre, wpre);
    };

    fetch(0);
    store(0);
    __syncthreads();

    for (int j = 0; j < totalCin; ++j) {
        const int cur = j & 1;
        if (j + 1 < totalCin) fetch(j + 1);   // LDG overlaps compute below

        // sliding window: 10 rows x 3 cols of input around this thread's column
        float f[10][3];
#pragma unroll
        for (int rr = 0; rr < 10; ++rr)
#pragma unroll
            for (int dx = 0; dx < 3; ++dx)
                f[rr][dx] = s_in[cur][(r0 + rr)*SROW + x + 3 + dx];

        // 27 shared vertical pairs: t[rp] = rows (rp, rp+1)
        unsigned long long t[9][3];
#pragma unroll
        for (int rp = 0; rp < 9; ++rp)
#pragma unroll
            for (int dx = 0; dx < 3; ++dx)
                t[rp][dx] = pack2(f[rp][dx], f[rp+1][dx]);

#pragma unroll
        for (int oo = 0; oo < 8; ++oo) {
            unsigned long long w[9];
#pragma unroll
            for (int k = 0; k < 9; ++k)
                w[k] = *(const unsigned long long*)&s_w[cur][oo*9 + k];
#pragma unroll
            for (int p = 0; p < 4; ++p)
#pragma unroll
                for (int dy = 0; dy < 3; ++dy)
#pragma unroll
                    for (int dx = 0; dx < 3; ++dx)
                        fma2(acc[oo*4 + p], t[2*p + dy][dx], w[dy*3 + dx]);
        }

        __syncthreads();                       // all done reading buf[cur^1]
        if (j + 1 < totalCin) {
            store(cur ^ 1);
            __syncthreads();                   // buf[cur^1] ready for next iter
        }
    }

    float* ob = out + (long)b * out_bstride;
#pragma unroll
    for (int oo = 0; oo < 8; ++oo) {
        int o = oBase + oo;
        float bias = b1[o] + (b2 ? b2[o] : 0.f);
#pragma unroll
        for (int p = 0; p < 4; ++p) {
            float2 v = unpack2(acc[oo*4 + p]);
            float* pp = ob + (long)o*HW + (y0 + r0 + 2*p)*WW + x;
            pp[0]  = v.x + bias;
            pp[WW] = v.y + bias;
        }
    }
}

// ---- fused LSTM pointwise: gates [i,f,g,o] -> update (h, c), float4 ----
static __device__ __forceinline__ float fsig(float x) {
    return __fdividef(1.f, 1.f + __expf(-x));
}
static __device__ __forceinline__ float ftanh(float x) {
    return __fdividef(2.f, 1.f + __expf(-2.f*x)) - 1.f;
}

__global__ void lstm_pointwise(float* __restrict__ hbuf, float* __restrict__ cbuf)
{
    const int n4 = BB*CH*HW/4;
    int idx = blockIdx.x*blockDim.x + threadIdx.x;
    if (idx >= n4) return;
    int e  = idx << 2;
    int p  = e & (HW - 1);
    int ch = (e >> 12) & (CH - 1);
    int b  = e >> 19;
    const float* gb = g_gates + (long)b * GG * HW;
    float4 gi = *(const float4*)(gb + (ch         )*HW + p);
    float4 gf = *(const float4*)(gb + (ch +   CH  )*HW + p);
    float4 gg = *(const float4*)(gb + (ch + 2*CH  )*HW + p);
    float4 go = *(const float4*)(gb + (ch + 3*CH  )*HW + p);
    float4 c  = *(float4*)(cbuf + e);
    float4 h;

    { float i_=fsig(gi.x), f_=fsig(gf.x), g_=ftanh(gg.x), o_=fsig(go.x);
      c.x = f_*c.x + i_*g_;  h.x = o_*ftanh(c.x); }
    { float i_=fsig(gi.y), f_=fsig(gf.y), g_=ftanh(gg.y), o_=fsig(go.y);
      c.y = f_*c.y + i_*g_;  h.y = o_*ftanh(c.y); }
    { float i_=fsig(gi.z), f_=fsig(gf.z), g_=ftanh(gg.z), o_=fsig(go.z);
      c.z = f_*c.z + i_*g_;  h.z = o_*ftanh(c.z); }
    { float i_=fsig(gi.w), f_=fsig(gf.w), g_=ftanh(gg.w), o_=fsig(go.w);
      c.w = f_*c.w + i_*g_;  h.w = o_*ftanh(c.w); }

    *(float4*)(cbuf + e) = c;
    *(float4*)(hbuf + e) = h;
}

extern "C" void kernel_launch(void* const* d_in, const int* in_sizes, int n_in,
                              void* d_out, int out_size)
{
    const float* target = (const float*)d_in[0];
    const float* h0     = (const float*)d_in[1];
    const float* c0     = (const float*)d_in[2];
    const float* h1     = (const float*)d_in[3];
    const float* c1     = (const float*)d_in[4];
    const float* wi0    = (const float*)d_in[5];
    const float* bi0    = (const float*)d_in[6];
    const float* wh0    = (const float*)d_in[7];
    const float* bh0    = (const float*)d_in[8];
    const float* wi1    = (const float*)d_in[9];
    const float* bi1    = (const float*)d_in[10];
    const float* wh1    = (const float*)d_in[11];
    const float* bh1    = (const float*)d_in[12];
    const float* wtop   = (const float*)d_in[13];
    const float* btop   = (const float*)d_in[14];
    float* out = (float*)d_out;

    float *ph0, *pc0, *ph1, *pc1, *pg;
    cudaGetSymbolAddress((void**)&ph0, g_h0);
    cudaGetSymbolAddress((void**)&pc0, g_c0);
    cudaGetSymbolAddress((void**)&ph1, g_h1);
    cudaGetSymbolAddress((void**)&pc1, g_c1);
    cudaGetSymbolAddress((void**)&pg,  g_gates);

    const long SB = (long)CH*HW;           // state batch stride
    const long TB = (long)TT*CX*HW;        // target/output batch stride
    const long GB = (long)GG*HW;           // gates batch stride

    init_states<<<4096, 256>>>(h0, c0, h1, c1);

    // out[:, 0] = conv(h1_initial, wtop) + btop
    conv3x3_kernel<<<dim3(2, CX/8, BB), 256>>>(
        h1, CH, SB, wtop, btop,
        nullptr, 0, nullptr, nullptr,
        out, TB);

    const int NPW4 = BB*CH*HW/4;
    for (int t = 0; t < TT - 1; ++t) {
        // layer 0: gates = conv(x_t, wi0)+bi0 + conv(h0, wh0)+bh0
        conv3x3_kernel<<<dim3(2, GG/8, BB), 256>>>(
            target + (long)t*CX*HW, CX, TB, wi0, bi0,
            ph0, CH, wh0, bh0,
            pg, GB);
        lstm_pointwise<<<(NPW4 + 255)/256, 256>>>(ph0, pc0);   // h0 <- x1

        // layer 1: gates = conv(x1, wi1)+bi1 + conv(h1, wh1)+bh1
        conv3x3_kernel<<<dim3(2, GG/8, BB), 256>>>(
            ph0, CH, SB, wi1, bi1,
            ph1, CH, wh1, bh1,
            pg, GB);
        lstm_pointwise<<<(NPW4 + 255)/256, 256>>>(ph1, pc1);   // h1 <- x2

        // out[:, t+1] = conv(x2, wtop) + btop
        conv3x3_kernel<<<dim3(2, CX/8, BB), 256>>>(
            ph1, CH, SB, wtop, btop,
            nullptr, 0, nullptr, nullptr,
            out + (long)(t+1)*CX*HW, TB);
    }
}

// round 9
// speedup vs baseline: 1.3353x; 1.3353x over previous
#include <cuda_runtime.h>
#include <cstdint>

// ConvDecoder: 2-layer ConvLSTM decoder.
// fp32 direct conv, FFMA2 (fma.rn.f32x2), 32x32 tile, 16 oc/block,
// 4 px/thread, cp.async double-buffered halo. 2 blocks/SM.
// B=8, T=10, C=64, CH=128, H=W=64, 3x3 SAME.

#define BB 8
#define TT 10
#define CX 64
#define CH 128
#define WW 64
#define HW 4096
#define GG (4*CH)   // 512 gate channels

// ---- persistent scratch (device globals; no allocation allowed) ----
__device__ float g_h0[BB*CH*HW];
__device__ float g_c0[BB*CH*HW];
__device__ float g_h1[BB*CH*HW];
__device__ float g_c1[BB*CH*HW];
__device__ float g_gates[BB*GG*HW];

// ---- packed f32x2 helpers ----
static __device__ __forceinline__ unsigned long long pack2(float lo, float hi) {
    unsigned long long r;
    asm("mov.b64 %0, {%1, %2};" : "=l"(r) : "f"(lo), "f"(hi));
    return r;
}
static __device__ __forceinline__ void fma2(unsigned long long& d,
                                            unsigned long long a,
                                            unsigned long long b) {
    asm("fma.rn.f32x2 %0, %1, %2, %0;" : "+l"(d) : "l"(a), "l"(b));
}
static __device__ __forceinline__ float2 unpack2(unsigned long long v) {
    float2 r;
    asm("mov.b64 {%0, %1}, %2;" : "=f"(r.x), "=f"(r.y) : "l"(v));
    return r;
}

// ---- cp.async helpers ----
static __device__ __forceinline__ void cpasync4(uint32_t dst, const float* src, int srcsize) {
    asm volatile("cp.async.ca.shared.global [%0], [%1], 4, %2;"
                 :: "r"(dst), "l"(src), "r"(srcsize) : "memory");
}
static __device__ __forceinline__ void cp_commit() {
    asm volatile("cp.async.commit_group;" ::: "memory");
}
static __device__ __forceinline__ void cp_wait1() {
    asm volatile("cp.async.wait_group 1;" ::: "memory");
}

__global__ void init_states(const float* __restrict__ h0, const float* __restrict__ c0,
                            const float* __restrict__ h1, const float* __restrict__ c1) {
    int n = BB*CH*HW;
    for (int i = blockIdx.x*blockDim.x + threadIdx.x; i < n; i += gridDim.x*blockDim.x) {
        g_h0[i] = h0[i];
        g_c0[i] = c0[i];
        g_h1[i] = h1[i];
        g_c1[i] = c1[i];
    }
}

// ---- fused 3x3 conv: out = conv(in1,w1)+b1 [+ conv(in2,w2)+b2] ----
// 32x32 output tile, 16 output channels per block, 256 threads.
// Each thread: 4 pixels (rows py, py+8, py+16, py+24) packed as 2 f32x2 pairs.
#define HALO (34*34)
__global__ __launch_bounds__(256, 2)
void conv3x3_kernel(const float* __restrict__ in1, int cin1, long in1_bstride,
                    const float* __restrict__ w1, const float* __restrict__ b1,
                    const float* __restrict__ in2, int cin2,
                    const float* __restrict__ w2, const float* __restrict__ b2,
                    float* __restrict__ out, long out_bstride)
{
    __shared__ float  s_in[2][HALO];
    __shared__ float2 s_w[2][16*9];

    const int tid   = threadIdx.x;
    const int tileX = blockIdx.x & 1;          // W/32 = 2
    const int tileY = blockIdx.x >> 1;         // H/32 = 2
    const int oBase = blockIdx.y * 16;
    const int b     = blockIdx.z;
    const int px    = tid & 31;
    const int py    = tid >> 5;                // 0..7

    const int x0 = tileX * 32;
    const int y0 = tileY * 32;

    // halo descriptors: enc = smem_idx[0:11) | gmem_off[11:23) | valid[23]
    int henc[5];
#pragma unroll
    for (int j = 0; j < 5; ++j) {
        int i = tid + j*256;
        int r = i / 34, c = i - r*34;
        int gy = y0 + r - 1, gx = x0 + c - 1;
        bool ok = (i < HALO) && ((unsigned)gy < 64u) && ((unsigned)gx < 64u);
        int g = ok ? (gy*WW + gx) : 0;
        henc[j] = (i < HALO ? i : 0) | (g << 11) | (ok ? (1 << 23) : 0);
    }
    const bool slot4 = (tid + 4*256) < HALO;

    const int  w_oo   = tid / 9;
    const int  w_k    = tid - w_oo * 9;
    const bool w_role = tid < 144;

    const float* in1b = in1 + (long)b * in1_bstride;
    const float* in2b = in2 ? (in2 + (long)b * ((long)CH*HW)) : nullptr;
    const int totalCin = cin1 + cin2;          // always >= 64

    const uint32_t sin_u32_0 = (uint32_t)__cvta_generic_to_shared(&s_in[0][0]);
    const uint32_t sin_u32_1 = (uint32_t)__cvta_generic_to_shared(&s_in[1][0]);

    auto halo_issue = [&](int j, int buf) {
        const float* ic = (j < cin1) ? (in1b + (long)j*HW)
                                     : (in2b + (long)(j - cin1)*HW);
        uint32_t sb = buf ? sin_u32_1 : sin_u32_0;
#pragma unroll
        for (int s = 0; s < 4; ++s) {
            int e = henc[s];
            cpasync4(sb + (uint32_t)(e & 0x7FF)*4u, ic + ((e >> 11) & 0xFFF),
                     (e >> 23) ? 4 : 0);
        }
        if (slot4) {
            int e = henc[4];
            cpasync4(sb + (uint32_t)(e & 0x7FF)*4u, ic + ((e >> 11) & 0xFFF),
                     (e >> 23) ? 4 : 0);
        }
    };
    auto wload = [&](int j) -> float {
        if (j < cin1) return w1[((oBase + w_oo)*cin1 + j)*9 + w_k];
        return w2[((oBase + w_oo)*cin2 + (j - cin1))*9 + w_k];
    };

    unsigned long long acc0[16], acc1[16];
    const unsigned long long z = pack2(0.f, 0.f);
#pragma unroll
    for (int i = 0; i < 16; ++i) { acc0[i] = z; acc1[i] = z; }

    // ---- pipeline prologue (totalCin >= 2 always) ----
    float wpre = 0.f;
    halo_issue(0, 0);
    cp_commit();                               // group for cin 0
    if (w_role) {
        float w0 = wload(0);
        s_w[0][tid] = make_float2(w0, w0);     // ordered by first __syncthreads
        wpre = wload(1);                       // weights for cin 1 in reg
    }
    halo_issue(1, 1);
    cp_commit();                               // group for cin 1

    for (int j = 0; j < totalCin; ++j) {
        const int cur = j & 1;
        cp_wait1();                            // halo for cin j resident
        __syncthreads();                       // + s_w[cur] visible

        // gather 4 pixels x 9 taps into packed registers
        unsigned long long a0[9], a1[9];
#pragma unroll
        for (int dy = 0; dy < 3; ++dy)
#pragma unroll
            for (int dx = 0; dx < 3; ++dx) {
                const float* base = &s_in[cur][(py + dy)*34 + (px + dx)];
                int k = dy*3 + dx;
                a0[k] = pack2(base[0],      base[8*34]);
                a1[k] = pack2(base[16*34],  base[24*34]);
            }
#pragma unroll
        for (int oo = 0; oo < 16; ++oo) {
#pragma unroll
            for (int k = 0; k < 9; ++k) {
                unsigned long long w =
                    *reinterpret_cast<const unsigned long long*>(&s_w[cur][oo*9 + k]);
                fma2(acc0[oo], a0[k], w);
                fma2(acc1[oo], a1[k], w);
            }
        }

        __syncthreads();                       // all reads of buf[cur] done
        if (j + 2 < totalCin) halo_issue(j + 2, cur);
        if (w_role && (j + 1 < totalCin)) {
            s_w[cur ^ 1][tid] = make_float2(wpre, wpre);   // weights for cin j+1
            if (j + 2 < totalCin) wpre = wload(j + 2);
        }
        cp_commit();                           // keep group counting uniform
    }

    float* ob = out + (long)b * out_bstride;
#pragma unroll
    for (int oo = 0; oo < 16; ++oo) {
        int o = oBase + oo;
        float bias = b1[o] + (b2 ? b2[o] : 0.f);
        float2 v0 = unpack2(acc0[oo]);
        float2 v1 = unpack2(acc1[oo]);
        float* p = ob + (long)o*HW + (y0 + py)*WW + (x0 + px);
        p[0]      = v0.x + bias;
        p[8*WW]   = v0.y + bias;
        p[16*WW]  = v1.x + bias;
        p[24*WW]  = v1.y + bias;
    }
}

// ---- fused LSTM pointwise: gates [i,f,g,o] -> update (h, c), float4 ----
static __device__ __forceinline__ float fsig(float x) {
    return __fdividef(1.f, 1.f + __expf(-x));
}
static __device__ __forceinline__ float ftanh(float x) {
    return __fdividef(2.f, 1.f + __expf(-2.f*x)) - 1.f;
}

__global__ void lstm_pointwise(float* __restrict__ hbuf, float* __restrict__ cbuf)
{
    const int n4 = BB*CH*HW/4;
    int idx = blockIdx.x*blockDim.x + threadIdx.x;
    if (idx >= n4) return;
    int e  = idx << 2;
    int p  = e & (HW - 1);
    int ch = (e >> 12) & (CH - 1);
    int b  = e >> 19;
    const float* gb = g_gates + (long)b * GG * HW;
    float4 gi = *(const float4*)(gb + (ch         )*HW + p);
    float4 gf = *(const float4*)(gb + (ch +   CH  )*HW + p);
    float4 gg = *(const float4*)(gb + (ch + 2*CH  )*HW + p);
    float4 go = *(const float4*)(gb + (ch + 3*CH  )*HW + p);
    float4 c  = *(float4*)(cbuf + e);
    float4 h;

    { float i_=fsig(gi.x), f_=fsig(gf.x), g_=ftanh(gg.x), o_=fsig(go.x);
      c.x = f_*c.x + i_*g_;  h.x = o_*ftanh(c.x); }
    { float i_=fsig(gi.y), f_=fsig(gf.y), g_=ftanh(gg.y), o_=fsig(go.y);
      c.y = f_*c.y + i_*g_;  h.y = o_*ftanh(c.y); }
    { float i_=fsig(gi.z), f_=fsig(gf.z), g_=ftanh(gg.z), o_=fsig(go.z);
      c.z = f_*c.z + i_*g_;  h.z = o_*ftanh(c.z); }
    { float i_=fsig(gi.w), f_=fsig(gf.w), g_=ftanh(gg.w), o_=fsig(go.w);
      c.w = f_*c.w + i_*g_;  h.w = o_*ftanh(c.w); }

    *(float4*)(cbuf + e) = c;
    *(float4*)(hbuf + e) = h;
}

extern "C" void kernel_launch(void* const* d_in, const int* in_sizes, int n_in,
                              void* d_out, int out_size)
{
    const float* target = (const float*)d_in[0];
    const float* h0     = (const float*)d_in[1];
    const float* c0     = (const float*)d_in[2];
    const float* h1     = (const float*)d_in[3];
    const float* c1     = (const float*)d_in[4];
    const float* wi0    = (const float*)d_in[5];
    const float* bi0    = (const float*)d_in[6];
    const float* wh0    = (const float*)d_in[7];
    const float* bh0    = (const float*)d_in[8];
    const float* wi1    = (const float*)d_in[9];
    const float* bi1    = (const float*)d_in[10];
    const float* wh1    = (const float*)d_in[11];
    const float* bh1    = (const float*)d_in[12];
    const float* wtop   = (const float*)d_in[13];
    const float* btop   = (const float*)d_in[14];
    float* out = (float*)d_out;

    float *ph0, *pc0, *ph1, *pc1, *pg;
    cudaGetSymbolAddress((void**)&ph0, g_h0);
    cudaGetSymbolAddress((void**)&pc0, g_c0);
    cudaGetSymbolAddress((void**)&ph1, g_h1);
    cudaGetSymbolAddress((void**)&pc1, g_c1);
    cudaGetSymbolAddress((void**)&pg,  g_gates);

    const long SB = (long)CH*HW;           // state batch stride
    const long TB = (long)TT*CX*HW;        // target/output batch stride
    const long GB = (long)GG*HW;           // gates batch stride

    init_states<<<4096, 256>>>(h0, c0, h1, c1);

    // out[:, 0] = conv(h1_initial, wtop) + btop
    conv3x3_kernel<<<dim3(4, CX/16, BB), 256>>>(
        h1, CH, SB, wtop, btop,
        nullptr, 0, nullptr, nullptr,
        out, TB);

    const int NPW4 = BB*CH*HW/4;
    for (int t = 0; t < TT - 1; ++t) {
        // layer 0: gates = conv(x_t, wi0)+bi0 + conv(h0, wh0)+bh0
        conv3x3_kernel<<<dim3(4, GG/16, BB), 256>>>(
            target + (long)t*CX*HW, CX, TB, wi0, bi0,
            ph0, CH, wh0, bh0,
            pg, GB);
        lstm_pointwise<<<(NPW4 + 255)/256, 256>>>(ph0, pc0);   // h0 <- x1

        // layer 1: gates = conv(x1, wi1)+bi1 + conv(h1, wh1)+bh1
        conv3x3_kernel<<<dim3(4, GG/16, BB), 256>>>(
            ph0, CH, SB, wi1, bi1,
            ph1, CH, wh1, bh1,
            pg, GB);
        lstm_pointwise<<<(NPW4 + 255)/256, 256>>>(ph1, pc1);   // h1 <- x2

        // out[:, t+1] = conv(x2, wtop) + btop
        conv3x3_kernel<<<dim3(4, CX/16, BB), 256>>>(
            ph1, CH, SB, wtop, btop,
            nullptr, 0, nullptr, nullptr,
            out + (long)(t+1)*CX*HW, TB);
    }
}

// round 11
// speedup vs baseline: 1.4086x; 1.0549x over previous
#include <cuda_runtime.h>
#include <cstdint>

// ConvDecoder: 2-layer ConvLSTM decoder.
// fp32 direct conv, FFMA2 (fma.rn.f32x2), 32x32 tile, 16 oc/block,
// 4 px/thread, 3-stage cp.async ring (1 barrier/cin), LDS.128 weight fetch.
// 2 blocks/SM. B=8, T=10, C=64, CH=128, H=W=64, 3x3 SAME.

#define BB 8
#define TT 10
#define CX 64
#define CH 128
#define WW 64
#define HW 4096
#define GG (4*CH)   // 512 gate channels

// ---- persistent scratch (device globals; no allocation allowed) ----
__device__ float g_h0[BB*CH*HW];
__device__ float g_c0[BB*CH*HW];
__device__ float g_h1[BB*CH*HW];
__device__ float g_c1[BB*CH*HW];
__device__ float g_gates[BB*GG*HW];

// ---- packed f32x2 helpers ----
static __device__ __forceinline__ unsigned long long pack2(float lo, float hi) {
    unsigned long long r;
    asm("mov.b64 %0, {%1, %2};" : "=l"(r) : "f"(lo), "f"(hi));
    return r;
}
static __device__ __forceinline__ void fma2(unsigned long long& d,
                                            unsigned long long a,
                                            unsigned long long b) {
    asm("fma.rn.f32x2 %0, %1, %2, %0;" : "+l"(d) : "l"(a), "l"(b));
}
static __device__ __forceinline__ float2 unpack2(unsigned long long v) {
    float2 r;
    asm("mov.b64 {%0, %1}, %2;" : "=f"(r.x), "=f"(r.y) : "l"(v));
    return r;
}

// ---- cp.async helpers ----
static __device__ __forceinline__ void cpasync4(uint32_t dst, const float* src, int srcsize) {
    asm volatile("cp.async.ca.shared.global [%0], [%1], 4, %2;"
                 :: "r"(dst), "l"(src), "r"(srcsize) : "memory");
}
static __device__ __forceinline__ void cp_commit() {
    asm volatile("cp.async.commit_group;" ::: "memory");
}
static __device__ __forceinline__ void cp_wait1() {
    asm volatile("cp.async.wait_group 1;" ::: "memory");
}

__global__ void init_states(const float* __restrict__ h0, const float* __restrict__ c0,
                            const float* __restrict__ h1, const float* __restrict__ c1) {
    int n = BB*CH*HW;
    for (int i = blockIdx.x*blockDim.x + threadIdx.x; i < n; i += gridDim.x*blockDim.x) {
        g_h0[i] = h0[i];
        g_c0[i] = c0[i];
        g_h1[i] = h1[i];
        g_c1[i] = c1[i];
    }
}

// ---- fused 3x3 conv: out = conv(in1,w1)+b1 [+ conv(in2,w2)+b2] ----
// 32x32 output tile, 16 output channels per block, 256 threads.
// Each thread: 4 pixels (rows py, py+8, py+16, py+24) packed as 2 f32x2 pairs.
#define HALO (34*34)
#define WSTRIDE 10      // float2 per oc row in s_w (16B aligned: 80B)

__global__ __launch_bounds__(256, 2)
void conv3x3_kernel(const float* __restrict__ in1, int cin1, long in1_bstride,
                    const float* __restrict__ w1, const float* __restrict__ b1,
                    const float* __restrict__ in2, int cin2,
                    const float* __restrict__ w2, const float* __restrict__ b2,
                    float* __restrict__ out, long out_bstride)
{
    __shared__ float s_in[3][HALO];
    __shared__ __align__(16) float2 s_w[3][16*WSTRIDE];

    const int tid   = threadIdx.x;
    const int tileX = blockIdx.x & 1;          // W/32 = 2
    const int tileY = blockIdx.x >> 1;         // H/32 = 2
    const int oBase = blockIdx.y * 16;
    const int b     = blockIdx.z;
    const int px    = tid & 31;
    const int py    = tid >> 5;                // 0..7

    const int x0 = tileX * 32;
    const int y0 = tileY * 32;

    // halo descriptors: enc = smem_idx[0:11) | gmem_off[11:23) | valid[23]
    int henc[5];
#pragma unroll
    for (int j = 0; j < 5; ++j) {
        int i = tid + j*256;
        int r = i / 34, c = i - r*34;
        int gy = y0 + r - 1, gx = x0 + c - 1;
        bool ok = (i < HALO) && ((unsigned)gy < 64u) && ((unsigned)gx < 64u);
        int g = ok ? (gy*WW + gx) : 0;
        henc[j] = (i < HALO ? i : 0) | (g << 11) | (ok ? (1 << 23) : 0);
    }
    const bool slot4 = (tid + 4*256) < HALO;

    const int  w_oo   = tid / 9;
    const int  w_k    = tid - w_oo * 9;
    const bool w_role = tid < 144;
    const int  w_idx  = w_oo * WSTRIDE + w_k;

    const float* in1b = in1 + (long)b * in1_bstride;
    const float* in2b = in2 ? (in2 + (long)b * ((long)CH*HW)) : nullptr;
    const int totalCin = cin1 + cin2;          // >= 64 always

    uint32_t sin_u32[3];
    sin_u32[0] = (uint32_t)__cvta_generic_to_shared(&s_in[0][0]);
    sin_u32[1] = (uint32_t)__cvta_generic_to_shared(&s_in[1][0]);
    sin_u32[2] = (uint32_t)__cvta_generic_to_shared(&s_in[2][0]);

    auto halo_issue = [&](int j, int buf) {
        const float* ic = (j < cin1) ? (in1b + (long)j*HW)
                                     : (in2b + (long)(j - cin1)*HW);
        uint32_t sb = sin_u32[buf];
#pragma unroll
        for (int s = 0; s < 4; ++s) {
            int e = henc[s];
            cpasync4(sb + (uint32_t)(e & 0x7FF)*4u, ic + ((e >> 11) & 0xFFF),
                     (e >> 23) ? 4 : 0);
        }
        if (slot4) {
            int e = henc[4];
            cpasync4(sb + (uint32_t)(e & 0x7FF)*4u, ic + ((e >> 11) & 0xFFF),
                     (e >> 23) ? 4 : 0);
        }
    };
    auto wload = [&](int j) -> float {
        if (j < cin1) return w1[((oBase + w_oo)*cin1 + j)*9 + w_k];
        return w2[((oBase + w_oo)*cin2 + (j - cin1))*9 + w_k];
    };

    unsigned long long acc0[16], acc1[16];
    const unsigned long long z = pack2(0.f, 0.f);
#pragma unroll
    for (int i = 0; i < 16; ++i) { acc0[i] = z; acc1[i] = z; }

    // ---- pipeline prologue ----
    float wpre = 0.f;
    halo_issue(0, 0);
    cp_commit();                               // group: cin 0
    halo_issue(1, 1);
    cp_commit();                               // group: cin 1
    if (w_role) {
        float t0 = wload(0);
        s_w[0][w_idx] = make_float2(t0, t0);
        float t1 = wload(1);
        s_w[1][w_idx] = make_float2(t1, t1);
        wpre = (2 < totalCin) ? wload(2) : 0.f;
    }

    for (int j = 0; j < totalCin; ++j) {
        const int cur = j - (j/3)*3;           // j % 3
        cp_wait1();                            // halo cin j resident (j+1 may fly)
        __syncthreads();                       // halo + weights for cin j visible;
                                               // all warps done computing cin j-1
        // refill ring slot (j+2)%3 == (j-1)%3 — free since compute j-1 finished
        if (j + 2 < totalCin) {
            int nbuf = cur + 2; if (nbuf >= 3) nbuf -= 3;
            halo_issue(j + 2, nbuf);
            if (w_role) {
                s_w[nbuf][w_idx] = make_float2(wpre, wpre);
                wpre = (j + 3 < totalCin) ? wload(j + 3) : 0.f;
            }
        }
        cp_commit();                           // uniform group accounting

        // gather 4 pixels x 9 taps into packed registers
        unsigned long long a0[9], a1[9];
#pragma unroll
        for (int dy = 0; dy < 3; ++dy)
#pragma unroll
            for (int dx = 0; dx < 3; ++dx) {
                const float* base = &s_in[cur][(py + dy)*34 + (px + dx)];
                int k = dy*3 + dx;
                a0[k] = pack2(base[0],      base[8*34]);
                a1[k] = pack2(base[16*34],  base[24*34]);
            }
#pragma unroll
        for (int oo = 0; oo < 16; ++oo) {
            // 9 duplicated weight pairs: 4x LDS.128 + 1x LDS.64 (broadcast)
            const ulonglong2* wrow =
                reinterpret_cast<const ulonglong2*>(&s_w[cur][oo*WSTRIDE]);
            ulonglong2 w01 = wrow[0];
            ulonglong2 w23 = wrow[1];
            ulonglong2 w45 = wrow[2];
            ulonglong2 w67 = wrow[3];
            unsigned long long w8 =
                *reinterpret_cast<const unsigned long long*>(&s_w[cur][oo*WSTRIDE + 8]);
            unsigned long long w[9] = {w01.x, w01.y, w23.x, w23.y,
                                       w45.x, w45.y, w67.x, w67.y, w8};
#pragma unroll
            for (int k = 0; k < 9; ++k) {
                fma2(acc0[oo], a0[k], w[k]);
                fma2(acc1[oo], a1[k], w[k]);
            }
        }
    }

    float* ob = out + (long)b * out_bstride;
#pragma unroll
    for (int oo = 0; oo < 16; ++oo) {
        int o = oBase + oo;
        float bias = b1[o] + (b2 ? b2[o] : 0.f);
        float2 v0 = unpack2(acc0[oo]);
        float2 v1 = unpack2(acc1[oo]);
        float* p = ob + (long)o*HW + (y0 + py)*WW + (x0 + px);
        p[0]      = v0.x + bias;
        p[8*WW]   = v0.y + bias;
        p[16*WW]  = v1.x + bias;
        p[24*WW]  = v1.y + bias;
    }
}

// ---- fused LSTM pointwise: gates [i,f,g,o] -> update (h, c), float4 ----
static __device__ __forceinline__ float fsig(float x) {
    return __fdividef(1.f, 1.f + __expf(-x));
}
static __device__ __forceinline__ float ftanh(float x) {
    return __fdividef(2.f, 1.f + __expf(-2.f*x)) - 1.f;
}

__global__ void lstm_pointwise(float* __restrict__ hbuf, float* __restrict__ cbuf)
{
    const int n4 = BB*CH*HW/4;
    int idx = blockIdx.x*blockDim.x + threadIdx.x;
    if (idx >= n4) return;
    int e  = idx << 2;
    int p  = e & (HW - 1);
    int ch = (e >> 12) & (CH - 1);
    int b  = e >> 19;
    const float* gb = g_gates + (long)b * GG * HW;
    float4 gi = *(const float4*)(gb + (ch         )*HW + p);
    float4 gf = *(const float4*)(gb + (ch +   CH  )*HW + p);
    float4 gg = *(const float4*)(gb + (ch + 2*CH  )*HW + p);
    float4 go = *(const float4*)(gb + (ch + 3*CH  )*HW + p);
    float4 c  = *(float4*)(cbuf + e);
    float4 h;

    { float i_=fsig(gi.x), f_=fsig(gf.x), g_=ftanh(gg.x), o_=fsig(go.x);
      c.x = f_*c.x + i_*g_;  h.x = o_*ftanh(c.x); }
    { float i_=fsig(gi.y), f_=fsig(gf.y), g_=ftanh(gg.y), o_=fsig(go.y);
      c.y = f_*c.y + i_*g_;  h.y = o_*ftanh(c.y); }
    { float i_=fsig(gi.z), f_=fsig(gf.z), g_=ftanh(gg.z), o_=fsig(go.z);
      c.z = f_*c.z + i_*g_;  h.z = o_*ftanh(c.z); }
    { float i_=fsig(gi.w), f_=fsig(gf.w), g_=ftanh(gg.w), o_=fsig(go.w);
      c.w = f_*c.w + i_*g_;  h.w = o_*ftanh(c.w); }

    *(float4*)(cbuf + e) = c;
    *(float4*)(hbuf + e) = h;
}

extern "C" void kernel_launch(void* const* d_in, const int* in_sizes, int n_in,
                              void* d_out, int out_size)
{
    const float* target = (const float*)d_in[0];
    const float* h0     = (const float*)d_in[1];
    const float* c0     = (const float*)d_in[2];
    const float* h1     = (const float*)d_in[3];
    const float* c1     = (const float*)d_in[4];
    const float* wi0    = (const float*)d_in[5];
    const float* bi0    = (const float*)d_in[6];
    const float* wh0    = (const float*)d_in[7];
    const float* bh0    = (const float*)d_in[8];
    const float* wi1    = (const float*)d_in[9];
    const float* bi1    = (const float*)d_in[10];
    const float* wh1    = (const float*)d_in[11];
    const float* bh1    = (const float*)d_in[12];
    const float* wtop   = (const float*)d_in[13];
    const float* btop   = (const float*)d_in[14];
    float* out = (float*)d_out;

    float *ph0, *pc0, *ph1, *pc1, *pg;
    cudaGetSymbolAddress((void**)&ph0, g_h0);
    cudaGetSymbolAddress((void**)&pc0, g_c0);
    cudaGetSymbolAddress((void**)&ph1, g_h1);
    cudaGetSymbolAddress((void**)&pc1, g_c1);
    cudaGetSymbolAddress((void**)&pg,  g_gates);

    const long SB = (long)CH*HW;           // state batch stride
    const long TB = (long)TT*CX*HW;        // target/output batch stride
    const long GB = (long)GG*HW;           // gates batch stride

    init_states<<<4096, 256>>>(h0, c0, h1, c1);

    // out[:, 0] = conv(h1_initial, wtop) + btop
    conv3x3_kernel<<<dim3(4, CX/16, BB), 256>>>(
        h1, CH, SB, wtop, btop,
        nullptr, 0, nullptr, nullptr,
        out, TB);

    const int NPW4 = BB*CH*HW/4;
    for (int t = 0; t < TT - 1; ++t) {
        // layer 0: gates = conv(x_t, wi0)+bi0 + conv(h0, wh0)+bh0
        conv3x3_kernel<<<dim3(4, GG/16, BB), 256>>>(
            target + (long)t*CX*HW, CX, TB, wi0, bi0,
            ph0, CH, wh0, bh0,
            pg, GB);
        lstm_pointwise<<<(NPW4 + 255)/256, 256>>>(ph0, pc0);   // h0 <- x1

        // layer 1: gates = conv(x1, wi1)+bi1 + conv(h1, wh1)+bh1
        conv3x3_kernel<<<dim3(4, GG/16, BB), 256>>>(
            ph0, CH, SB, wi1, bi1,
            ph1, CH, wh1, bh1,
            pg, GB);
        lstm_pointwise<<<(NPW4 + 255)/256, 256>>>(ph1, pc1);   // h1 <- x2

        // out[:, t+1] = conv(x2, wtop) + btop
        conv3x3_kernel<<<dim3(4, CX/16, BB), 256>>>(
            ph1, CH, SB, wtop, btop,
            nullptr, 0, nullptr, nullptr,
            out + (long)(t+1)*CX*HW, TB);
    }
}

// round 12
// speedup vs baseline: 1.5296x; 1.0859x over previous
#include <cuda_runtime.h>
#include <cstdint>

// ConvDecoder: 2-layer ConvLSTM decoder.
// fp32 direct conv, FFMA2 (fma.rn.f32x2), 32x32 tile, 16 oc/block,
// 4 px/thread, 3-slot cp.async ring with 2 cin per stage (1 barrier / 2 cin),
// LDS.128 weight fetch. 2 blocks/SM. B=8, T=10, C=64, CH=128, 64x64, 3x3 SAME.

#define BB 8
#define TT 10
#define CX 64
#define CH 128
#define WW 64
#define HW 4096
#define GG (4*CH)   // 512 gate channels

// ---- persistent scratch (device globals; no allocation allowed) ----
__device__ float g_h0[BB*CH*HW];
__device__ float g_c0[BB*CH*HW];
__device__ float g_h1[BB*CH*HW];
__device__ float g_c1[BB*CH*HW];
__device__ float g_gates[BB*GG*HW];

// ---- packed f32x2 helpers ----
static __device__ __forceinline__ unsigned long long pack2(float lo, float hi) {
    unsigned long long r;
    asm("mov.b64 %0, {%1, %2};" : "=l"(r) : "f"(lo), "f"(hi));
    return r;
}
static __device__ __forceinline__ void fma2(unsigned long long& d,
                                            unsigned long long a,
                                            unsigned long long b) {
    asm("fma.rn.f32x2 %0, %1, %2, %0;" : "+l"(d) : "l"(a), "l"(b));
}
static __device__ __forceinline__ float2 unpack2(unsigned long long v) {
    float2 r;
    asm("mov.b64 {%0, %1}, %2;" : "=f"(r.x), "=f"(r.y) : "l"(v));
    return r;
}

// ---- cp.async helpers ----
static __device__ __forceinline__ void cpasync4(uint32_t dst, const float* src, int srcsize) {
    asm volatile("cp.async.ca.shared.global [%0], [%1], 4, %2;"
                 :: "r"(dst), "l"(src), "r"(srcsize) : "memory");
}
static __device__ __forceinline__ void cp_commit() {
    asm volatile("cp.async.commit_group;" ::: "memory");
}
static __device__ __forceinline__ void cp_wait1() {
    asm volatile("cp.async.wait_group 1;" ::: "memory");
}

__global__ void init_states(const float* __restrict__ h0, const float* __restrict__ c0,
                            const float* __restrict__ h1, const float* __restrict__ c1) {
    int n = BB*CH*HW;
    for (int i = blockIdx.x*blockDim.x + threadIdx.x; i < n; i += gridDim.x*blockDim.x) {
        g_h0[i] = h0[i];
        g_c0[i] = c0[i];
        g_h1[i] = h1[i];
        g_c1[i] = c1[i];
    }
}

// ---- fused 3x3 conv: out = conv(in1,w1)+b1 [+ conv(in2,w2)+b2] ----
// 32x32 output tile, 16 output channels per block, 256 threads.
// Each thread: 4 pixels (rows py, py+8, py+16, py+24) packed as 2 f32x2 pairs.
// Pipeline: 3-slot ring, each slot = 2 input channels (halo + weights).
#define HALO (34*34)
#define WSTRIDE 10      // float2 per oc row in s_w (16B aligned: 80B)

__global__ __launch_bounds__(256, 2)
void conv3x3_kernel(const float* __restrict__ in1, int cin1, long in1_bstride,
                    const float* __restrict__ w1, const float* __restrict__ b1,
                    const float* __restrict__ in2, int cin2,
                    const float* __restrict__ w2, const float* __restrict__ b2,
                    float* __restrict__ out, long out_bstride)
{
    __shared__ float s_in[3][2][HALO];
    __shared__ __align__(16) float2 s_w[3][2][16*WSTRIDE];

    const int tid   = threadIdx.x;
    const int tileX = blockIdx.x & 1;          // W/32 = 2
    const int tileY = blockIdx.x >> 1;         // H/32 = 2
    const int oBase = blockIdx.y * 16;
    const int b     = blockIdx.z;
    const int px    = tid & 31;
    const int py    = tid >> 5;                // 0..7

    const int x0 = tileX * 32;
    const int y0 = tileY * 32;

    // halo descriptors: enc = smem_idx[0:11) | gmem_off[11:23) | valid[23]
    int henc[5];
#pragma unroll
    for (int j = 0; j < 5; ++j) {
        int i = tid + j*256;
        int r = i / 34, c = i - r*34;
        int gy = y0 + r - 1, gx = x0 + c - 1;
        bool ok = (i < HALO) && ((unsigned)gy < 64u) && ((unsigned)gx < 64u);
        int g = ok ? (gy*WW + gx) : 0;
        henc[j] = (i < HALO ? i : 0) | (g << 11) | (ok ? (1 << 23) : 0);
    }
    const bool slot4 = (tid + 4*256) < HALO;

    const int  w_oo   = tid / 9;
    const int  w_k    = tid - w_oo * 9;
    const bool w_role = tid < 144;
    const int  w_idx  = w_oo * WSTRIDE + w_k;

    const float* in1b = in1 + (long)b * in1_bstride;
    const float* in2b = in2 ? (in2 + (long)b * ((long)CH*HW)) : nullptr;
    const int totalCin = cin1 + cin2;          // even, >= 192
    const int S = totalCin >> 1;               // stages (2 cin each), >= 96

    auto chanptr = [&](int j) -> const float* {
        return (j < cin1) ? (in1b + (long)j*HW) : (in2b + (long)(j - cin1)*HW);
    };

    auto halo_issue2 = [&](int s, int slot) {   // halos for cins 2s, 2s+1
        const float* ic0 = chanptr(2*s);
        const float* ic1 = chanptr(2*s + 1);
        uint32_t sb0 = (uint32_t)__cvta_generic_to_shared(&s_in[slot][0][0]);
        uint32_t sb1 = (uint32_t)__cvta_generic_to_shared(&s_in[slot][1][0]);
#pragma unroll
        for (int q = 0; q < 4; ++q) {
            int e = henc[q];
            uint32_t so = (uint32_t)(e & 0x7FF)*4u;
            const int  go = (e >> 11) & 0xFFF;
            const int  sz = (e >> 23) ? 4 : 0;
            cpasync4(sb0 + so, ic0 + go, sz);
            cpasync4(sb1 + so, ic1 + go, sz);
        }
        if (slot4) {
            int e = henc[4];
            uint32_t so = (uint32_t)(e & 0x7FF)*4u;
            const int  go = (e >> 11) & 0xFFF;
            const int  sz = (e >> 23) ? 4 : 0;
            cpasync4(sb0 + so, ic0 + go, sz);
            cpasync4(sb1 + so, ic1 + go, sz);
        }
    };
    auto wload1 = [&](int j) -> float {
        if (j < cin1) return w1[((oBase + w_oo)*cin1 + j)*9 + w_k];
        return w2[((oBase + w_oo)*cin2 + (j - cin1))*9 + w_k];
    };

    unsigned long long acc0[16], acc1[16];
    const unsigned long long z = pack2(0.f, 0.f);
#pragma unroll
    for (int i = 0; i < 16; ++i) { acc0[i] = z; acc1[i] = z; }

    // ---- pipeline prologue (S >= 3 always) ----
    float2 wpre = make_float2(0.f, 0.f);
    halo_issue2(0, 0);
    cp_commit();                               // group: stage 0
    halo_issue2(1, 1);
    cp_commit();                               // group: stage 1
    if (w_role) {
        float t0 = wload1(0), t1 = wload1(1);
        s_w[0][0][w_idx] = make_float2(t0, t0);
        s_w[0][1][w_idx] = make_float2(t1, t1);
        float t2 = wload1(2), t3 = wload1(3);
        s_w[1][0][w_idx] = make_float2(t2, t2);
        s_w[1][1][w_idx] = make_float2(t3, t3);
        wpre.x = wload1(4);
        wpre.y = wload1(5);                    // weights for stage 2
    }

    for (int s = 0; s < S; ++s) {
        const int cur = s - (s/3)*3;           // s % 3
        cp_wait1();                            // stage s halos resident
        __syncthreads();                       // + weights visible; compute s-1 done

        // refill ring slot (s+2)%3 == (s-1)%3
        if (s + 2 < S) {
            int nbuf = cur + 2; if (nbuf >= 3) nbuf -= 3;
            halo_issue2(s + 2, nbuf);
            if (w_role) {
                s_w[nbuf][0][w_idx] = make_float2(wpre.x, wpre.x);
                s_w[nbuf][1][w_idx] = make_float2(wpre.y, wpre.y);
                if (s + 3 < S) {
                    wpre.x = wload1(2*s + 6);
                    wpre.y = wload1(2*s + 7);
                }
            }
        }
        cp_commit();                           // uniform group accounting

#pragma unroll
        for (int sub = 0; sub < 2; ++sub) {
            // gather 4 pixels x 9 taps into packed registers
            unsigned long long a0[9], a1[9];
#pragma unroll
            for (int dy = 0; dy < 3; ++dy)
#pragma unroll
                for (int dx = 0; dx < 3; ++dx) {
                    const float* base = &s_in[cur][sub][(py + dy)*34 + (px + dx)];
                    int k = dy*3 + dx;
                    a0[k] = pack2(base[0],      base[8*34]);
                    a1[k] = pack2(base[16*34],  base[24*34]);
                }
#pragma unroll
            for (int oo = 0; oo < 16; ++oo) {
                // 9 duplicated weight pairs: 4x LDS.128 + 1x LDS.64 (broadcast)
                const ulonglong2* wrow =
                    reinterpret_cast<const ulonglong2*>(&s_w[cur][sub][oo*WSTRIDE]);
                ulonglong2 w01 = wrow[0];
                ulonglong2 w23 = wrow[1];
                ulonglong2 w45 = wrow[2];
                ulonglong2 w67 = wrow[3];
                unsigned long long w8 =
                    *reinterpret_cast<const unsigned long long*>(
                        &s_w[cur][sub][oo*WSTRIDE + 8]);
                unsigned long long w[9] = {w01.x, w01.y, w23.x, w23.y,
                                           w45.x, w45.y, w67.x, w67.y, w8};
#pragma unroll
                for (int k = 0; k < 9; ++k) {
                    fma2(acc0[oo], a0[k], w[k]);
                    fma2(acc1[oo], a1[k], w[k]);
                }
            }
        }
    }

    float* ob = out + (long)b * out_bstride;
#pragma unroll
    for (int oo = 0; oo < 16; ++oo) {
        int o = oBase + oo;
        float bias = b1[o] + (b2 ? b2[o] : 0.f);
        float2 v0 = unpack2(acc0[oo]);
        float2 v1 = unpack2(acc1[oo]);
        float* p = ob + (long)o*HW + (y0 + py)*WW + (x0 + px);
        p[0]      = v0.x + bias;
        p[8*WW]   = v0.y + bias;
        p[16*WW]  = v1.x + bias;
        p[24*WW]  = v1.y + bias;
    }
}

// ---- fused LSTM pointwise: gates [i,f,g,o] -> update (h, c), float4 ----
static __device__ __forceinline__ float fsig(float x) {
    return __fdividef(1.f, 1.f + __expf(-x));
}
static __device__ __forceinline__ float ftanh(float x) {
    return __fdividef(2.f, 1.f + __expf(-2.f*x)) - 1.f;
}

__global__ void lstm_pointwise(float* __restrict__ hbuf, float* __restrict__ cbuf)
{
    const int n4 = BB*CH*HW/4;
    int idx = blockIdx.x*blockDim.x + threadIdx.x;
    if (idx >= n4) return;
    int e  = idx << 2;
    int p  = e & (HW - 1);
    int ch = (e >> 12) & (CH - 1);
    int b  = e >> 19;
    const float* gb = g_gates + (long)b * GG * HW;
    float4 gi = *(const float4*)(gb + (ch         )*HW + p);
    float4 gf = *(const float4*)(gb + (ch +   CH  )*HW + p);
    float4 gg = *(const float4*)(gb + (ch + 2*CH  )*HW + p);
    float4 go = *(const float4*)(gb + (ch + 3*CH  )*HW + p);
    float4 c  = *(float4*)(cbuf + e);
    float4 h;

    { float i_=fsig(gi.x), f_=fsig(gf.x), g_=ftanh(gg.x), o_=fsig(go.x);
      c.x = f_*c.x + i_*g_;  h.x = o_*ftanh(c.x); }
    { float i_=fsig(gi.y), f_=fsig(gf.y), g_=ftanh(gg.y), o_=fsig(go.y);
      c.y = f_*c.y + i_*g_;  h.y = o_*ftanh(c.y); }
    { float i_=fsig(gi.z), f_=fsig(gf.z), g_=ftanh(gg.z), o_=fsig(go.z);
      c.z = f_*c.z + i_*g_;  h.z = o_*ftanh(c.z); }
    { float i_=fsig(gi.w), f_=fsig(gf.w), g_=ftanh(gg.w), o_=fsig(go.w);
      c.w = f_*c.w + i_*g_;  h.w = o_*ftanh(c.w); }

    *(float4*)(cbuf + e) = c;
    *(float4*)(hbuf + e) = h;
}

extern "C" void kernel_launch(void* const* d_in, const int* in_sizes, int n_in,
                              void* d_out, int out_size)
{
    const float* target = (const float*)d_in[0];
    const float* h0     = (const float*)d_in[1];
    const float* c0     = (const float*)d_in[2];
    const float* h1     = (const float*)d_in[3];
    const float* c1     = (const float*)d_in[4];
    const float* wi0    = (const float*)d_in[5];
    const float* bi0    = (const float*)d_in[6];
    const float* wh0    = (const float*)d_in[7];
    const float* bh0    = (const float*)d_in[8];
    const float* wi1    = (const float*)d_in[9];
    const float* bi1    = (const float*)d_in[10];
    const float* wh1    = (const float*)d_in[11];
    const float* bh1    = (const float*)d_in[12];
    const float* wtop   = (const float*)d_in[13];
    const float* btop   = (const float*)d_in[14];
    float* out = (float*)d_out;

    float *ph0, *pc0, *ph1, *pc1, *pg;
    cudaGetSymbolAddress((void**)&ph0, g_h0);
    cudaGetSymbolAddress((void**)&pc0, g_c0);
    cudaGetSymbolAddress((void**)&ph1, g_h1);
    cudaGetSymbolAddress((void**)&pc1, g_c1);
    cudaGetSymbolAddress((void**)&pg,  g_gates);

    const long SB = (long)CH*HW;           // state batch stride
    const long TB = (long)TT*CX*HW;        // target/output batch stride
    const long GB = (long)GG*HW;           // gates batch stride

    init_states<<<4096, 256>>>(h0, c0, h1, c1);

    // out[:, 0] = conv(h1_initial, wtop) + btop
    conv3x3_kernel<<<dim3(4, CX/16, BB), 256>>>(
        h1, CH, SB, wtop, btop,
        nullptr, 0, nullptr, nullptr,
        out, TB);

    const int NPW4 = BB*CH*HW/4;
    for (int t = 0; t < TT - 1; ++t) {
        // layer 0: gates = conv(x_t, wi0)+bi0 + conv(h0, wh0)+bh0
        conv3x3_kernel<<<dim3(4, GG/16, BB), 256>>>(
            target + (long)t*CX*HW, CX, TB, wi0, bi0,
            ph0, CH, wh0, bh0,
            pg, GB);
        lstm_pointwise<<<(NPW4 + 255)/256, 256>>>(ph0, pc0);   // h0 <- x1

        // layer 1: gates = conv(x1, wi1)+bi1 + conv(h1, wh1)+bh1
        conv3x3_kernel<<<dim3(4, GG/16, BB), 256>>>(
            ph0, CH, SB, wi1, bi1,
            ph1, CH, wh1, bh1,
            pg, GB);
        lstm_pointwise<<<(NPW4 + 255)/256, 256>>>(ph1, pc1);   // h1 <- x2

        // out[:, t+1] = conv(x2, wtop) + btop
        conv3x3_kernel<<<dim3(4, CX/16, BB), 256>>>(
            ph1, CH, SB, wtop, btop,
            nullptr, 0, nullptr, nullptr,
            out + (long)(t+1)*CX*HW, TB);
    }
}

// round 15
// speedup vs baseline: 2.9122x; 1.9039x over previous
#include <cuda_runtime.h>
#include <cuda_bf16.h>
#include <cstdint>

// ConvDecoder via mma.sync bf16 implicit GEMM (hi/lo split, f32 accum).
// tcgen05 is unavailable (harness PTX target is base sm_103), so we use the
// arch-portable ldmatrix + mma.sync.m16n8k16 path.
// B=8, T=10, C=64, CH=128, H=W=64, 3x3 SAME.

#define BB 8
#define TT 10
#define CX 64
#define CH 128
#define WW 64
#define HW 4096
#define GG 512

// ---------------- persistent device-global scratch ----------------
__device__ float g_h0[BB*CH*HW];
__device__ float g_c0[BB*CH*HW];
__device__ float g_h1[BB*CH*HW];
__device__ float g_c1[BB*CH*HW];
__device__ float g_gates[BB*GG*HW];

// pixel-major bf16 activations (hi/lo): Xt[b][px][cin]
__device__ __nv_bfloat16 g_xtx_h[9L*BB*HW*CX];
__device__ __nv_bfloat16 g_xtx_l[9L*BB*HW*CX];
__device__ __nv_bfloat16 g_xth0_h[(long)BB*HW*CH];
__device__ __nv_bfloat16 g_xth0_l[(long)BB*HW*CH];
__device__ __nv_bfloat16 g_xth1_h[(long)BB*HW*CH];
__device__ __nv_bfloat16 g_xth1_l[(long)BB*HW*CH];

// pre-swizzled A-tiles (128 oc x 64 cin bf16, SW128 row-major), per (m,tap,chunk)
__device__ __nv_bfloat16 g_wL0_h[4*9*3*8192];
__device__ __nv_bfloat16 g_wL0_l[4*9*3*8192];
__device__ __nv_bfloat16 g_wL1_h[4*9*4*8192];
__device__ __nv_bfloat16 g_wL1_l[4*9*4*8192];
__device__ __nv_bfloat16 g_wTP_h[9*2*8192];
__device__ __nv_bfloat16 g_wTP_l[9*2*8192];

// ---------------- helpers ----------------
#define SWZ128(off) ((off) ^ (((off) >> 3) & 0x70))

static __device__ __forceinline__ uint32_t smem_u32(const void* p) {
    return (uint32_t)__cvta_generic_to_shared(p);
}
static __device__ __forceinline__ void cp16(uint32_t dst, const void* src, int sz) {
    asm volatile("cp.async.cg.shared.global [%0], [%1], 16, %2;"
                 :: "r"(dst), "l"(src), "r"(sz) : "memory");
}
static __device__ __forceinline__ void cp_commit() {
    asm volatile("cp.async.commit_group;" ::: "memory");
}
static __device__ __forceinline__ void cp_wait0() {
    asm volatile("cp.async.wait_group 0;" ::: "memory");
}
static __device__ __forceinline__ void ldmx4(uint32_t* r, uint32_t a) {
    asm volatile("ldmatrix.sync.aligned.m8n8.x4.shared.b16 {%0,%1,%2,%3}, [%4];"
                 : "=r"(r[0]), "=r"(r[1]), "=r"(r[2]), "=r"(r[3]) : "r"(a));
}
static __device__ __forceinline__ void mma_bf16(float* d, const uint32_t* a,
                                                uint32_t b0, uint32_t b1) {
    asm volatile("mma.sync.aligned.m16n8k16.row.col.f32.bf16.bf16.f32 "
                 "{%0,%1,%2,%3}, {%4,%5,%6,%7}, {%8,%9}, {%0,%1,%2,%3};"
                 : "+f"(d[0]), "+f"(d[1]), "+f"(d[2]), "+f"(d[3])
                 : "r"(a[0]), "r"(a[1]), "r"(a[2]), "r"(a[3]), "r"(b0), "r"(b1));
}

// ---------------- small kernels ----------------
__global__ void init_states(const float* __restrict__ h0, const float* __restrict__ c0,
                            const float* __restrict__ h1, const float* __restrict__ c1) {
    int n = BB*CH*HW;
    for (int i = blockIdx.x*blockDim.x + threadIdx.x; i < n; i += gridDim.x*blockDim.x) {
        g_h0[i] = h0[i]; g_c0[i] = c0[i];
        g_h1[i] = h1[i]; g_c1[i] = c1[i];
    }
}

// weights -> pre-swizzled bf16 hi/lo A-tiles ([oc][cin] 128B rows, SW128)
__global__ void prep_weights(const float* __restrict__ w1, int cin1,
                             const float* __restrict__ w2, int cin2,
                             int CO, int co_pad,
                             __nv_bfloat16* __restrict__ dh, __nv_bfloat16* __restrict__ dl)
{
    int cinT = cin1 + cin2;
    int chunks = cinT >> 6;
    long total = (long)co_pad * cinT * 9;
    for (long idx = (long)blockIdx.x*blockDim.x + threadIdx.x; idx < total;
         idx += (long)gridDim.x*blockDim.x) {
        int tap = (int)(idx % 9);
        long t2 = idx / 9;
        int cinG = (int)(t2 % cinT);
        int ocp  = (int)(t2 / cinT);
        float v = 0.f;
        if (ocp < CO)
            v = (cinG < cin1) ? w1[((long)ocp*cin1 + cinG)*9 + tap]
                              : w2[((long)ocp*cin2 + (cinG - cin1))*9 + tap];
        __nv_bfloat16 h = __float2bfloat16(v);
        __nv_bfloat16 l = __float2bfloat16(v - __bfloat162float(h));
        int mm = ocp >> 7, ocl = ocp & 127, cc = cinG >> 6, cl = cinG & 63;
        long tile = (long)(mm*9 + tap)*chunks + cc;
        int off = SWZ128(ocl*128 + cl*2);
        *(__nv_bfloat16*)((char*)dh + tile*16384 + off) = h;
        *(__nv_bfloat16*)((char*)dl + tile*16384 + off) = l;
    }
}

// f32 [b][C][4096] -> pixel-major bf16 hi/lo [b][4096][C]
__global__ void transpose_bf16(const float* __restrict__ in, long inBstride,
                               __nv_bfloat16* __restrict__ oh, __nv_bfloat16* __restrict__ ol,
                               int C)
{
    __shared__ float tbuf[32][33];
    int b = blockIdx.z;
    int pxb = blockIdx.x*32, chb = blockIdx.y*32;
    const float* ib = in + (long)b*inBstride;
#pragma unroll
    for (int j = 0; j < 4; ++j) {
        int ch = chb + threadIdx.y + j*8;
        tbuf[threadIdx.y + j*8][threadIdx.x] = ib[(long)ch*HW + pxb + threadIdx.x];
    }
    __syncthreads();
    long ob = (long)b*HW*C;
#pragma unroll
    for (int j = 0; j < 4; ++j) {
        int px = pxb + threadIdx.y + j*8;
        float v = tbuf[threadIdx.x][threadIdx.y + j*8];
        __nv_bfloat16 h = __float2bfloat16(v);
        long o = ob + (long)px*C + chb + threadIdx.x;
        oh[o] = h;
        ol[o] = __float2bfloat16(v - __bfloat162float(h));
    }
}

// ---------------- mma.sync conv GEMM ----------------
// grid: (BB*32 pixel-tiles, Mtiles). CTA: 256 thr / 8 warps, tile 128oc x 128px.
// Warp (warp_m = wid>>2, warp_n = wid&3) computes 64oc x 32px.
#define GEMM_SMEM (64*1024)

__global__ __launch_bounds__(256, 2)
void conv_mma(const char* __restrict__ x1h, const char* __restrict__ x1l, int chunks1,
              const char* __restrict__ x2h, const char* __restrict__ x2l, int chunks2,
              const __nv_bfloat16* __restrict__ wAh, const __nv_bfloat16* __restrict__ wAl,
              const float* __restrict__ b1, const float* __restrict__ b2,
              float* __restrict__ outp, long obstride, int co_real)
{
    extern __shared__ __align__(128) char dsm[];
    const uint32_t Ah32 = smem_u32(dsm);
    const uint32_t Al32 = Ah32 + 16384;
    const uint32_t Bh32 = Ah32 + 32768;
    const uint32_t Bl32 = Ah32 + 49152;

    const int tid = threadIdx.x, wid = tid >> 5, lane = tid & 31;
    const int warp_m = wid >> 2;               // 0..1
    const int warp_n = wid & 3;                // 0..3
    const int m  = blockIdx.y;
    const int bx = blockIdx.x;
    const int b  = bx >> 5;
    const int p0 = (bx & 31) * 128;            // 128 pixels = 2 image rows

    // B gather role: thread loads half of one pixel row
    const int p_local = tid >> 1;              // 0..127
    const int half    = tid & 1;               // 64B halves
    const int pout = p0 + p_local;
    const int py = pout >> 6, pxx = pout & 63;

    // ldmatrix lane addressing (shared by A and B)
    const int lrow = lane & 15;
    const int lkb  = (lane >> 4) << 4;         // 0 or 16 bytes

    const int chunks = chunks1 + chunks2;
    const int S = 9 * chunks;
    const int rb1 = chunks1 * 128, rb2 = chunks2 * 128;   // bytes per pixel row

    float acc[4][4][4];
#pragma unroll
    for (int i = 0; i < 4; ++i)
#pragma unroll
        for (int j = 0; j < 4; ++j)
#pragma unroll
            for (int q = 0; q < 4; ++q) acc[i][j][q] = 0.f;

    for (int s = 0; s < S; ++s) {
        const int tap = s / chunks;
        const int c   = s - tap*chunks;
        const int dy  = tap/3 - 1;
        const int dx  = (tap - (tap/3)*3) - 1;

        // A: linear copy of pre-swizzled 16KB hi/lo tiles
        {
            long tile = (long)(m*9 + tap)*chunks + c;
            const char* wsH = (const char*)wAh + tile*16384;
            const char* wsL = (const char*)wAl + tile*16384;
#pragma unroll
            for (int i = 0; i < 4; ++i) {
                int u = tid + i*256;
                cp16(Ah32 + u*16, wsH + u*16, 16);
                cp16(Al32 + u*16, wsL + u*16, 16);
            }
        }
        // B: half a 128B pixel row per thread, swizzled dst, OOB zero-fill
        {
            int ys = py + dy, xs = pxx + dx;
            bool ok = ((unsigned)ys < 64u) && ((unsigned)xs < 64u);
            long psrc = ok ? ((long)b*HW + ys*64 + xs) : 0;
            const char *sh, *sl; int rb, coff;
            if (c < chunks1) { sh = x1h; sl = x1l; rb = rb1; coff = c*128; }
            else             { sh = x2h; sl = x2l; rb = rb2; coff = (c - chunks1)*128; }
            const char* rowH = sh + psrc*rb + coff + half*64;
            const char* rowL = sl + psrc*rb + coff + half*64;
            int sz = ok ? 16 : 0;
#pragma unroll
            for (int q = 0; q < 4; ++q) {
                uint32_t so = SWZ128(p_local*128 + half*64 + q*16);
                cp16(Bh32 + so, rowH + q*16, sz);
                cp16(Bl32 + so, rowL + q*16, sz);
            }
        }
        cp_commit();
        cp_wait0();
        __syncthreads();

        // 3-way hi/lo split: (Ah,Bh), (Ah,Bl), (Al,Bh)
#pragma unroll
        for (int split = 0; split < 3; ++split) {
            const uint32_t Asel = (split == 2) ? Al32 : Ah32;
            const uint32_t Bsel = (split == 1) ? Bl32 : Bh32;
#pragma unroll
            for (int kk = 0; kk < 4; ++kk) {
                uint32_t br[2][4];
#pragma unroll
                for (int pair = 0; pair < 2; ++pair) {
                    uint32_t addr = Bsel +
                        SWZ128((uint32_t)((warp_n*32 + pair*16 + lrow) << 7) + kk*32 + lkb);
                    ldmx4(br[pair], addr);
                }
#pragma unroll
                for (int mt = 0; mt < 4; ++mt) {
                    uint32_t a[4];
                    uint32_t addr = Asel +
                        SWZ128((uint32_t)((warp_m*64 + mt*16 + lrow) << 7) + kk*32 + lkb);
                    ldmx4(a, addr);
                    mma_bf16(acc[mt][0], a, br[0][0], br[0][2]);
                    mma_bf16(acc[mt][1], a, br[0][1], br[0][3]);
                    mma_bf16(acc[mt][2], a, br[1][0], br[1][2]);
                    mma_bf16(acc[mt][3], a, br[1][1], br[1][3]);
                }
            }
        }
        __syncthreads();
    }

    // epilogue: c-frag -> gmem with bias
    const int ocbase = m*128 + warp_m*64;
    if (ocbase < co_real) {
        float* obb = outp + (long)b*obstride;
#pragma unroll
        for (int mt = 0; mt < 4; ++mt) {
#pragma unroll
            for (int m8 = 0; m8 < 2; ++m8) {
                int oc = ocbase + mt*16 + (lane >> 2) + m8*8;
                float bias = b1[oc] + (b2 ? b2[oc] : 0.f);
                float* orow = obb + (long)oc*HW;
#pragma unroll
                for (int nt = 0; nt < 4; ++nt) {
                    int px = p0 + warp_n*32 + nt*8 + 2*(lane & 3);
                    float2 v;
                    v.x = acc[mt][nt][m8*2 + 0] + bias;
                    v.y = acc[mt][nt][m8*2 + 1] + bias;
                    *(float2*)(orow + px) = v;
                }
            }
        }
    }
}

// ---------------- fused LSTM pointwise ----------------
static __device__ __forceinline__ float fsig(float x) {
    return __fdividef(1.f, 1.f + __expf(-x));
}
static __device__ __forceinline__ float ftanh(float x) {
    return __fdividef(2.f, 1.f + __expf(-2.f*x)) - 1.f;
}

__global__ void lstm_pointwise(float* __restrict__ hbuf, float* __restrict__ cbuf)
{
    const int n4 = BB*CH*HW/4;
    int idx = blockIdx.x*blockDim.x + threadIdx.x;
    if (idx >= n4) return;
    int e  = idx << 2;
    int p  = e & (HW - 1);
    int ch = (e >> 12) & (CH - 1);
    int b  = e >> 19;
    const float* gb = g_gates + (long)b * GG * HW;
    float4 gi = *(const float4*)(gb + (ch        )*HW + p);
    float4 gf = *(const float4*)(gb + (ch +   CH )*HW + p);
    float4 gg = *(const float4*)(gb + (ch + 2*CH )*HW + p);
    float4 go = *(const float4*)(gb + (ch + 3*CH )*HW + p);
    float4 c  = *(float4*)(cbuf + e);
    float4 h;

    { float i_=fsig(gi.x), f_=fsig(gf.x), g_=ftanh(gg.x), o_=fsig(go.x);
      c.x = f_*c.x + i_*g_;  h.x = o_*ftanh(c.x); }
    { float i_=fsig(gi.y), f_=fsig(gf.y), g_=ftanh(gg.y), o_=fsig(go.y);
      c.y = f_*c.y + i_*g_;  h.y = o_*ftanh(c.y); }
    { float i_=fsig(gi.z), f_=fsig(gf.z), g_=ftanh(gg.z), o_=fsig(go.z);
      c.z = f_*c.z + i_*g_;  h.z = o_*ftanh(c.z); }
    { float i_=fsig(gi.w), f_=fsig(gf.w), g_=ftanh(gg.w), o_=fsig(go.w);
      c.w = f_*c.w + i_*g_;  h.w = o_*ftanh(c.w); }

    *(float4*)(cbuf + e) = c;
    *(float4*)(hbuf + e) = h;
}

// ---------------- orchestration ----------------
extern "C" void kernel_launch(void* const* d_in, const int* in_sizes, int n_in,
                              void* d_out, int out_size)
{
    const float* target = (const float*)d_in[0];
    const float* h0     = (const float*)d_in[1];
    const float* c0     = (const float*)d_in[2];
    const float* h1     = (const float*)d_in[3];
    const float* c1     = (const float*)d_in[4];
    const float* wi0    = (const float*)d_in[5];
    const float* bi0    = (const float*)d_in[6];
    const float* wh0    = (const float*)d_in[7];
    const float* bh0    = (const float*)d_in[8];
    const float* wi1    = (const float*)d_in[9];
    const float* bi1    = (const float*)d_in[10];
    const float* wh1    = (const float*)d_in[11];
    const float* bh1    = (const float*)d_in[12];
    const float* wtop   = (const float*)d_in[13];
    const float* btop   = (const float*)d_in[14];
    float* out = (float*)d_out;

    cudaFuncSetAttribute(conv_mma, cudaFuncAttributeMaxDynamicSharedMemorySize, GEMM_SMEM);

    float *ph0, *pc0, *ph1, *pc1, *pg;
    cudaGetSymbolAddress((void**)&ph0, g_h0);
    cudaGetSymbolAddress((void**)&pc0, g_c0);
    cudaGetSymbolAddress((void**)&ph1, g_h1);
    cudaGetSymbolAddress((void**)&pc1, g_c1);
    cudaGetSymbolAddress((void**)&pg,  g_gates);

    __nv_bfloat16 *xtxh, *xtxl, *xh0h, *xh0l, *xh1h, *xh1l;
    cudaGetSymbolAddress((void**)&xtxh, g_xtx_h);
    cudaGetSymbolAddress((void**)&xtxl, g_xtx_l);
    cudaGetSymbolAddress((void**)&xh0h, g_xth0_h);
    cudaGetSymbolAddress((void**)&xh0l, g_xth0_l);
    cudaGetSymbolAddress((void**)&xh1h, g_xth1_h);
    cudaGetSymbolAddress((void**)&xh1l, g_xth1_l);

    __nv_bfloat16 *wL0h, *wL0l, *wL1h, *wL1l, *wTPh, *wTPl;
    cudaGetSymbolAddress((void**)&wL0h, g_wL0_h);
    cudaGetSymbolAddress((void**)&wL0l, g_wL0_l);
    cudaGetSymbolAddress((void**)&wL1h, g_wL1_h);
    cudaGetSymbolAddress((void**)&wL1l, g_wL1_l);
    cudaGetSymbolAddress((void**)&wTPh, g_wTP_h);
    cudaGetSymbolAddress((void**)&wTPl, g_wTP_l);

    const long TB = (long)TT*CX*HW;    // target/output batch stride
    const long GB = (long)GG*HW;       // gates batch stride

    init_states<<<4096, 256>>>(h0, c0, h1, c1);

    // pre-swizzled bf16 hi/lo weight tiles
    prep_weights<<<2048, 256>>>(wi0,  64, wh0, 128, 512, 512, wL0h, wL0l);
    prep_weights<<<2048, 256>>>(wi1, 128, wh1, 128, 512, 512, wL1h, wL1l);
    prep_weights<<<1024, 256>>>(wtop,128, nullptr, 0,  64, 128, wTPh, wTPl);

    // target -> pixel-major bf16 hi/lo (all 9 steps)
    dim3 tgrid64(128, CX/32, BB), tgrid128(128, CH/32, BB), tblk(32, 8);
    for (int t = 0; t < TT - 1; ++t)
        transpose_bf16<<<tgrid64, tblk>>>(target + (long)t*CX*HW, TB,
                                          xtxh + (long)t*BB*HW*CX,
                                          xtxl + (long)t*BB*HW*CX, CX);
    transpose_bf16<<<tgrid128, tblk>>>(ph0, (long)CH*HW, xh0h, xh0l, CH);
    transpose_bf16<<<tgrid128, tblk>>>(ph1, (long)CH*HW, xh1h, xh1l, CH);

    dim3 ggrid(BB*32, 4), pgrid(BB*32, 1);
    const int NPW4 = BB*CH*HW/4;

    // out[:, 0] = topconv(h1_initial)
    conv_mma<<<pgrid, 256, GEMM_SMEM>>>(
        (const char*)xh1h, (const char*)xh1l, 2,
        (const char*)xh1h, (const char*)xh1l, 0,
        wTPh, wTPl, btop, nullptr, out, TB, 64);

    for (int t = 0; t < TT - 1; ++t) {
        // layer 0 gates: [x_t (1 chunk) | h0 (2 chunks)]
        conv_mma<<<ggrid, 256, GEMM_SMEM>>>(
            (const char*)(xtxh + (long)t*BB*HW*CX),
            (const char*)(xtxl + (long)t*BB*HW*CX), 1,
            (const char*)xh0h, (const char*)xh0l, 2,
            wL0h, wL0l, bi0, bh0, pg, GB, 512);
        lstm_pointwise<<<(NPW4 + 255)/256, 256>>>(ph0, pc0);
        transpose_bf16<<<tgrid128, tblk>>>(ph0, (long)CH*HW, xh0h, xh0l, CH);

        // layer 1 gates: [x1 (2 chunks) | h1 (2 chunks)]
        conv_mma<<<ggrid, 256, GEMM_SMEM>>>(
            (const char*)xh0h, (const char*)xh0l, 2,
            (const char*)xh1h, (const char*)xh1l, 2,
            wL1h, wL1l, bi1, bh1, pg, GB, 512);
        lstm_pointwise<<<(NPW4 + 255)/256, 256>>>(ph1, pc1);
        transpose_bf16<<<tgrid128, tblk>>>(ph1, (long)CH*HW, xh1h, xh1l, CH);

        // out[:, t+1] = topconv(h1)
        conv_mma<<<pgrid, 256, GEMM_SMEM>>>(
            (const char*)xh1h, (const char*)xh1l, 2,
            (const char*)xh1h, (const char*)xh1l, 0,
            wTPh, wTPl, btop, nullptr, out + (long)(t+1)*CX*HW, TB, 64);
    }
}

// round 17
// speedup vs baseline: 4.1200x; 1.4147x over previous
#include <cuda_runtime.h>
#include <cuda_fp16.h>
#include <cstdint>

// ConvDecoder via mma.sync fp16 implicit GEMM (hi/lo activation split, f32 accum).
// 2 MMA passes: Wh*Xh + Wh*Xl (dropped Wl*X term ~2^-12 relative).
// B=8, T=10, C=64, CH=128, H=W=64, 3x3 SAME.

#define BB 8
#define TT 10
#define CX 64
#define CH 128
#define WW 64
#define HW 4096
#define GG 512

// ---------------- persistent device-global scratch ----------------
__device__ float g_h0[BB*CH*HW];
__device__ float g_c0[BB*CH*HW];
__device__ float g_h1[BB*CH*HW];
__device__ float g_c1[BB*CH*HW];
__device__ float g_gates[BB*GG*HW];

// pixel-major fp16 activations (hi/lo): Xt[b][px][cin]
__device__ __half g_xtx_h[9L*BB*HW*CX];
__device__ __half g_xtx_l[9L*BB*HW*CX];
__device__ __half g_xth0_h[(long)BB*HW*CH];
__device__ __half g_xth0_l[(long)BB*HW*CH];
__device__ __half g_xth1_h[(long)BB*HW*CH];
__device__ __half g_xth1_l[(long)BB*HW*CH];

// pre-swizzled A-tiles (128 oc x 64 cin fp16, SW128 row-major), per (m,tap,chunk)
__device__ __half g_wL0[4*9*3*8192];
__device__ __half g_wL1[4*9*4*8192];
__device__ __half g_wTP[9*2*8192];

// ---------------- helpers ----------------
#define SWZ128(off) ((off) ^ (((off) >> 3) & 0x70))

static __device__ __forceinline__ uint32_t smem_u32(const void* p) {
    return (uint32_t)__cvta_generic_to_shared(p);
}
static __device__ __forceinline__ void cp16(uint32_t dst, const void* src, int sz) {
    asm volatile("cp.async.cg.shared.global [%0], [%1], 16, %2;"
                 :: "r"(dst), "l"(src), "r"(sz) : "memory");
}
static __device__ __forceinline__ void cp_commit() {
    asm volatile("cp.async.commit_group;" ::: "memory");
}
static __device__ __forceinline__ void cp_wait0() {
    asm volatile("cp.async.wait_group 0;" ::: "memory");
}
static __device__ __forceinline__ void ldmx4(uint32_t* r, uint32_t a) {
    asm volatile("ldmatrix.sync.aligned.m8n8.x4.shared.b16 {%0,%1,%2,%3}, [%4];"
                 : "=r"(r[0]), "=r"(r[1]), "=r"(r[2]), "=r"(r[3]) : "r"(a));
}
static __device__ __forceinline__ void mma_f16(float* d, const uint32_t* a,
                                               uint32_t b0, uint32_t b1) {
    asm volatile("mma.sync.aligned.m16n8k16.row.col.f32.f16.f16.f32 "
                 "{%0,%1,%2,%3}, {%4,%5,%6,%7}, {%8,%9}, {%0,%1,%2,%3};"
                 : "+f"(d[0]), "+f"(d[1]), "+f"(d[2]), "+f"(d[3])
                 : "r"(a[0]), "r"(a[1]), "r"(a[2]), "r"(a[3]), "r"(b0), "r"(b1));
}

// ---------------- small kernels ----------------
__global__ void init_states(const float* __restrict__ h0, const float* __restrict__ c0,
                            const float* __restrict__ h1, const float* __restrict__ c1) {
    int n = BB*CH*HW;
    for (int i = blockIdx.x*blockDim.x + threadIdx.x; i < n; i += gridDim.x*blockDim.x) {
        g_h0[i] = h0[i]; g_c0[i] = c0[i];
        g_h1[i] = h1[i]; g_c1[i] = c1[i];
    }
}

// weights -> pre-swizzled fp16 A-tiles ([oc][cin] 128B rows, SW128)
__global__ void prep_weights(const float* __restrict__ w1, int cin1,
                             const float* __restrict__ w2, int cin2,
                             int CO, int co_pad,
                             __half* __restrict__ dh)
{
    int cinT = cin1 + cin2;
    int chunks = cinT >> 6;
    long total = (long)co_pad * cinT * 9;
    for (long idx = (long)blockIdx.x*blockDim.x + threadIdx.x; idx < total;
         idx += (long)gridDim.x*blockDim.x) {
        int tap = (int)(idx % 9);
        long t2 = idx / 9;
        int cinG = (int)(t2 % cinT);
        int ocp  = (int)(t2 / cinT);
        float v = 0.f;
        if (ocp < CO)
            v = (cinG < cin1) ? w1[((long)ocp*cin1 + cinG)*9 + tap]
                              : w2[((long)ocp*cin2 + (cinG - cin1))*9 + tap];
        int mm = ocp >> 7, ocl = ocp & 127, cc = cinG >> 6, cl = cinG & 63;
        long tile = (long)(mm*9 + tap)*chunks + cc;
        int off = SWZ128(ocl*128 + cl*2);
        *(__half*)((char*)dh + tile*16384 + off) = __float2half(v);
    }
}

// f32 [b][C][4096] -> pixel-major fp16 hi/lo [b][4096][C]
__global__ void transpose_f16(const float* __restrict__ in, long inBstride,
                              __half* __restrict__ oh, __half* __restrict__ ol,
                              int C)
{
    __shared__ float tbuf[32][33];
    int b = blockIdx.z;
    int pxb = blockIdx.x*32, chb = blockIdx.y*32;
    const float* ib = in + (long)b*inBstride;
#pragma unroll
    for (int j = 0; j < 4; ++j) {
        int ch = chb + threadIdx.y + j*8;
        tbuf[threadIdx.y + j*8][threadIdx.x] = ib[(long)ch*HW + pxb + threadIdx.x];
    }
    __syncthreads();
    long ob = (long)b*HW*C;
#pragma unroll
    for (int j = 0; j < 4; ++j) {
        int px = pxb + threadIdx.y + j*8;
        float v = tbuf[threadIdx.x][threadIdx.y + j*8];
        __half h = __float2half(v);
        long o = ob + (long)px*C + chb + threadIdx.x;
        oh[o] = h;
        ol[o] = __float2half(v - __half2float(h));
    }
}

// ---------------- mma.sync conv GEMM ----------------
// grid: (BB*32 pixel-tiles, Mtiles). CTA: 256 thr / 8 warps, tile 128oc x 128px.
// Warp (warp_m = wid>>2, warp_n = wid&3) computes 64oc x 32px.
// smem: Ah 16KB | Bh 16KB | Bl 16KB = 48KB
#define GEMM_SMEM (48*1024)

__global__ __launch_bounds__(256, 2)
void conv_mma(const char* __restrict__ x1h, const char* __restrict__ x1l, int chunks1,
              const char* __restrict__ x2h, const char* __restrict__ x2l, int chunks2,
              const __half* __restrict__ wA,
              const float* __restrict__ b1, const float* __restrict__ b2,
              float* __restrict__ outp, long obstride, int co_real)
{
    extern __shared__ __align__(128) char dsm[];
    const uint32_t Ah32 = smem_u32(dsm);
    const uint32_t Bh32 = Ah32 + 16384;
    const uint32_t Bl32 = Ah32 + 32768;

    const int tid = threadIdx.x, wid = tid >> 5, lane = tid & 31;
    const int warp_m = wid >> 2;               // 0..1
    const int warp_n = wid & 3;                // 0..3
    const int m  = blockIdx.y;
    const int bx = blockIdx.x;
    const int b  = bx >> 5;
    const int p0 = (bx & 31) * 128;            // 128 pixels = 2 image rows

    // B gather role: thread loads half of one pixel row
    const int p_local = tid >> 1;              // 0..127
    const int half    = tid & 1;               // 64B halves
    const int pout = p0 + p_local;
    const int py = pout >> 6, pxx = pout & 63;

    // ldmatrix lane addressing (shared by A and B)
    const int lrow = lane & 15;
    const int lkb  = (lane >> 4) << 4;         // 0 or 16 bytes

    const int chunks = chunks1 + chunks2;
    const int S = 9 * chunks;
    const int rb1 = chunks1 * 128, rb2 = chunks2 * 128;   // bytes per pixel row

    float acc[4][4][4];
#pragma unroll
    for (int i = 0; i < 4; ++i)
#pragma unroll
        for (int j = 0; j < 4; ++j)
#pragma unroll
            for (int q = 0; q < 4; ++q) acc[i][j][q] = 0.f;

    for (int s = 0; s < S; ++s) {
        const int tap = s / chunks;
        const int c   = s - tap*chunks;
        const int dy  = tap/3 - 1;
        const int dx  = (tap - (tap/3)*3) - 1;

        // A: linear copy of pre-swizzled 16KB tile
        {
            long tile = (long)(m*9 + tap)*chunks + c;
            const char* ws = (const char*)wA + tile*16384;
#pragma unroll
            for (int i = 0; i < 4; ++i) {
                int u = tid + i*256;
                cp16(Ah32 + u*16, ws + u*16, 16);
            }
        }
        // B: half a 128B pixel row per thread (hi+lo), swizzled dst, OOB zero-fill
        {
            int ys = py + dy, xs = pxx + dx;
            bool ok = ((unsigned)ys < 64u) && ((unsigned)xs < 64u);
            long psrc = ok ? ((long)b*HW + ys*64 + xs) : 0;
            const char *sh, *sl; int rb, coff;
            if (c < chunks1) { sh = x1h; sl = x1l; rb = rb1; coff = c*128; }
            else             { sh = x2h; sl = x2l; rb = rb2; coff = (c - chunks1)*128; }
            const char* rowH = sh + psrc*rb + coff + half*64;
            const char* rowL = sl + psrc*rb + coff + half*64;
            int sz = ok ? 16 : 0;
#pragma unroll
            for (int q = 0; q < 4; ++q) {
                uint32_t so = SWZ128(p_local*128 + half*64 + q*16);
                cp16(Bh32 + so, rowH + q*16, sz);
                cp16(Bl32 + so, rowL + q*16, sz);
            }
        }
        cp_commit();
        cp_wait0();
        __syncthreads();

        // 2 passes: (Ah,Bh) + (Ah,Bl); dropped Wl*X term ~2^-12 relative
#pragma unroll
        for (int split = 0; split < 2; ++split) {
            const uint32_t Bsel = split ? Bl32 : Bh32;
#pragma unroll
            for (int kk = 0; kk < 4; ++kk) {
                uint32_t br[2][4];
#pragma unroll
                for (int pair = 0; pair < 2; ++pair) {
                    uint32_t addr = Bsel +
                        SWZ128((uint32_t)((warp_n*32 + pair*16 + lrow) << 7) + kk*32 + lkb);
                    ldmx4(br[pair], addr);
                }
#pragma unroll
                for (int mt = 0; mt < 4; ++mt) {
                    uint32_t a[4];
                    uint32_t addr = Ah32 +
                        SWZ128((uint32_t)((warp_m*64 + mt*16 + lrow) << 7) + kk*32 + lkb);
                    ldmx4(a, addr);
                    mma_f16(acc[mt][0], a, br[0][0], br[0][2]);
                    mma_f16(acc[mt][1], a, br[0][1], br[0][3]);
                    mma_f16(acc[mt][2], a, br[1][0], br[1][2]);
                    mma_f16(acc[mt][3], a, br[1][1], br[1][3]);
                }
            }
        }
        __syncthreads();
    }

    // epilogue: c-frag -> gmem with bias
    const int ocbase = m*128 + warp_m*64;
    if (ocbase < co_real) {
        float* obb = outp + (long)b*obstride;
#pragma unroll
        for (int mt = 0; mt < 4; ++mt) {
#pragma unroll
            for (int m8 = 0; m8 < 2; ++m8) {
                int oc = ocbase + mt*16 + (lane >> 2) + m8*8;
                float bias = b1[oc] + (b2 ? b2[oc] : 0.f);
                float* orow = obb + (long)oc*HW;
#pragma unroll
                for (int nt = 0; nt < 4; ++nt) {
                    int px = p0 + warp_n*32 + nt*8 + 2*(lane & 3);
                    float2 v;
                    v.x = acc[mt][nt][m8*2 + 0] + bias;
                    v.y = acc[mt][nt][m8*2 + 1] + bias;
                    *(float2*)(orow + px) = v;
                }
            }
        }
    }
}

// ---------------- fused LSTM pointwise ----------------
static __device__ __forceinline__ float fsig(float x) {
    return __fdividef(1.f, 1.f + __expf(-x));
}
static __device__ __forceinline__ float ftanh(float x) {
    return __fdividef(2.f, 1.f + __expf(-2.f*x)) - 1.f;
}

__global__ void lstm_pointwise(float* __restrict__ hbuf, float* __restrict__ cbuf)
{
    const int n4 = BB*CH*HW/4;
    int idx = blockIdx.x*blockDim.x + threadIdx.x;
    if (idx >= n4) return;
    int e  = idx << 2;
    int p  = e & (HW - 1);
    int ch = (e >> 12) & (CH - 1);
    int b  = e >> 19;
    const float* gb = g_gates + (long)b * GG * HW;
    float4 gi = *(const float4*)(gb + (ch        )*HW + p);
    float4 gf = *(const float4*)(gb + (ch +   CH )*HW + p);
    float4 gg = *(const float4*)(gb + (ch + 2*CH )*HW + p);
    float4 go = *(const float4*)(gb + (ch + 3*CH )*HW + p);
    float4 c  = *(float4*)(cbuf + e);
    float4 h;

    { float i_=fsig(gi.x), f_=fsig(gf.x), g_=ftanh(gg.x), o_=fsig(go.x);
      c.x = f_*c.x + i_*g_;  h.x = o_*ftanh(c.x); }
    { float i_=fsig(gi.y), f_=fsig(gf.y), g_=ftanh(gg.y), o_=fsig(go.y);
      c.y = f_*c.y + i_*g_;  h.y = o_*ftanh(c.y); }
    { float i_=fsig(gi.z), f_=fsig(gf.z), g_=ftanh(gg.z), o_=fsig(go.z);
      c.z = f_*c.z + i_*g_;  h.z = o_*ftanh(c.z); }
    { float i_=fsig(gi.w), f_=fsig(gf.w), g_=ftanh(gg.w), o_=fsig(go.w);
      c.w = f_*c.w + i_*g_;  h.w = o_*ftanh(c.w); }

    *(float4*)(cbuf + e) = c;
    *(float4*)(hbuf + e) = h;
}

// ---------------- orchestration ----------------
extern "C" void kernel_launch(void* const* d_in, const int* in_sizes, int n_in,
                              void* d_out, int out_size)
{
    const float* target = (const float*)d_in[0];
    const float* h0     = (const float*)d_in[1];
    const float* c0     = (const float*)d_in[2];
    const float* h1     = (const float*)d_in[3];
    const float* c1     = (const float*)d_in[4];
    const float* wi0    = (const float*)d_in[5];
    const float* bi0    = (const float*)d_in[6];
    const float* wh0    = (const float*)d_in[7];
    const float* bh0    = (const float*)d_in[8];
    const float* wi1    = (const float*)d_in[9];
    const float* bi1    = (const float*)d_in[10];
    const float* wh1    = (const float*)d_in[11];
    const float* bh1    = (const float*)d_in[12];
    const float* wtop   = (const float*)d_in[13];
    const float* btop   = (const float*)d_in[14];
    float* out = (float*)d_out;

    cudaFuncSetAttribute(conv_mma, cudaFuncAttributeMaxDynamicSharedMemorySize, GEMM_SMEM);

    float *ph0, *pc0, *ph1, *pc1, *pg;
    cudaGetSymbolAddress((void**)&ph0, g_h0);
    cudaGetSymbolAddress((void**)&pc0, g_c0);
    cudaGetSymbolAddress((void**)&ph1, g_h1);
    cudaGetSymbolAddress((void**)&pc1, g_c1);
    cudaGetSymbolAddress((void**)&pg,  g_gates);

    __half *xtxh, *xtxl, *xh0h, *xh0l, *xh1h, *xh1l;
    cudaGetSymbolAddress((void**)&xtxh, g_xtx_h);
    cudaGetSymbolAddress((void**)&xtxl, g_xtx_l);
    cudaGetSymbolAddress((void**)&xh0h, g_xth0_h);
    cudaGetSymbolAddress((void**)&xh0l, g_xth0_l);
    cudaGetSymbolAddress((void**)&xh1h, g_xth1_h);
    cudaGetSymbolAddress((void**)&xh1l, g_xth1_l);

    __half *wL0, *wL1, *wTP;
    cudaGetSymbolAddress((void**)&wL0, g_wL0);
    cudaGetSymbolAddress((void**)&wL1, g_wL1);
    cudaGetSymbolAddress((void**)&wTP, g_wTP);

    const long TB = (long)TT*CX*HW;    // target/output batch stride
    const long GB = (long)GG*HW;       // gates batch stride

    init_states<<<4096, 256>>>(h0, c0, h1, c1);

    // pre-swizzled fp16 weight tiles
    prep_weights<<<2048, 256>>>(wi0,  64, wh0, 128, 512, 512, wL0);
    prep_weights<<<2048, 256>>>(wi1, 128, wh1, 128, 512, 512, wL1);
    prep_weights<<<1024, 256>>>(wtop,128, nullptr, 0,  64, 128, wTP);

    // target -> pixel-major fp16 hi/lo (all 9 steps)
    dim3 tgrid64(128, CX/32, BB), tgrid128(128, CH/32, BB), tblk(32, 8);
    for (int t = 0; t < TT - 1; ++t)
        transpose_f16<<<tgrid64, tblk>>>(target + (long)t*CX*HW, TB,
                                         xtxh + (long)t*BB*HW*CX,
                                         xtxl + (long)t*BB*HW*CX, CX);
    transpose_f16<<<tgrid128, tblk>>>(ph0, (long)CH*HW, xh0h, xh0l, CH);
    transpose_f16<<<tgrid128, tblk>>>(ph1, (long)CH*HW, xh1h, xh1l, CH);

    dim3 ggrid(BB*32, 4), pgrid(BB*32, 1);
    const int NPW4 = BB*CH*HW/4;

    // out[:, 0] = topconv(h1_initial)
    conv_mma<<<pgrid, 256, GEMM_SMEM>>>(
        (const char*)xh1h, (const char*)xh1l, 2,
        (const char*)xh1h, (const char*)xh1l, 0,
        wTP, btop, nullptr, out, TB, 64);

    for (int t = 0; t < TT - 1; ++t) {
        // layer 0 gates: [x_t (1 chunk) | h0 (2 chunks)]
        conv_mma<<<ggrid, 256, GEMM_SMEM>>>(
            (const char*)(xtxh + (long)t*BB*HW*CX),
            (const char*)(xtxl + (long)t*BB*HW*CX), 1,
            (const char*)xh0h, (const char*)xh0l, 2,
            wL0, bi0, bh0, pg, GB, 512);
        lstm_pointwise<<<(NPW4 + 255)/256, 256>>>(ph0, pc0);
        transpose_f16<<<tgrid128, tblk>>>(ph0, (long)CH*HW, xh0h, xh0l, CH);

        // layer 1 gates: [x1 (2 chunks) | h1 (2 chunks)]
        conv_mma<<<ggrid, 256, GEMM_SMEM>>>(
            (const char*)xh0h, (const char*)xh0l, 2,
            (const char*)xh1h, (const char*)xh1l, 2,
            wL1, bi1, bh1, pg, GB, 512);
        lstm_pointwise<<<(NPW4 + 255)/256, 256>>>(ph1, pc1);
        transpose_f16<<<tgrid128, tblk>>>(ph1, (long)CH*HW, xh1h, xh1l, CH);

        // out[:, t+1] = topconv(h1)
        conv_mma<<<pgrid, 256, GEMM_SMEM>>>(
            (const char*)xh1h, (const char*)xh1l, 2,
            (const char*)xh1h, (const char*)xh1l, 0,
            wTP, btop, nullptr, out + (long)(t+1)*CX*HW, TB, 64);
    }
}